// round 12
// baseline (speedup 1.0000x reference)
#include <cuda_runtime.h>
#include <math.h>
#include <stdint.h>

#define B_ 2048
#define F_ 128
#define U_ 1024
#define V_ 512
#define C_ 10

// ---------------- global scratch ----------------
__device__ float g_logits[B_ * C_];
__device__ float g_bsum[C_];
// prefix tables: for each f, rows j=0..1024 of (S1[j][v], P2[j][v]) pairs
__device__ float2 g_tab[(size_t)F_ * 1025 * 512];     // 537 MB
__device__ float  g_T2 [F_ * 512];                    // total e*W per (f,v)
__device__ float  g_thr[F_ * 1024];                   // sorted thresholds (asc)
__device__ float  g_es [F_ * 1024];                   // e at sorted order
__device__ int    g_ord[F_ * 1024];                   // original u index
__device__ float  g_cont0[F_ * C_];                   // relu(b1)@W2 (x<=0 path)

__device__ __forceinline__ uint32_t smem_u32(const void* p) {
    uint32_t a;
    asm("{ .reg .u64 t; cvta.to.shared.u64 t, %1; cvt.u32.u64 %0, t; }" : "=r"(a) : "l"(p));
    return a;
}
__device__ __forceinline__ void cpa4(uint32_t dst, const void* src) {
    asm volatile("cp.async.ca.shared.global [%0], [%1], 4;" :: "r"(dst), "l"(src));
}
#define CP_COMMIT() asm volatile("cp.async.commit_group;")
#define CP_WAIT(n)  asm volatile("cp.async.wait_group %0;" :: "n"(n))

// ---------------------------------------------------------------------------
// Kernel 0: per-feature sort of exu_w (descending w == ascending thr) +
// misc init (zero logits, bsum, cont0). Grid F_, 512 threads.
// ---------------------------------------------------------------------------
__global__ void __launch_bounds__(512)
nam_sort_kernel(const float* __restrict__ exu_w,
                const float* __restrict__ b1,
                const float* __restrict__ W2,
                const float* __restrict__ b2,
                const float* __restrict__ b_out) {
    const int f = blockIdx.x;
    const int tid = threadIdx.x;
    __shared__ float key[1024];
    __shared__ int   idx[1024];

    // key = -w  (ascending key == ascending thr = exp(-w))
    key[tid]       = -exu_w[f * U_ + tid];
    key[tid + 512] = -exu_w[f * U_ + tid + 512];
    idx[tid] = tid; idx[tid + 512] = tid + 512;
    __syncthreads();

    for (int k = 2; k <= 1024; k <<= 1) {
        for (int j = k >> 1; j > 0; j >>= 1) {
            #pragma unroll
            for (int h = 0; h < 2; h++) {
                int i = tid + h * 512;
                int ixj = i ^ j;
                if (ixj > i) {
                    bool up = ((i & k) == 0);
                    float a = key[i], b = key[ixj];
                    if ((a > b) == up) {
                        key[i] = b; key[ixj] = a;
                        int ti = idx[i]; idx[i] = idx[ixj]; idx[ixj] = ti;
                    }
                }
            }
            __syncthreads();
        }
    }

    #pragma unroll
    for (int h = 0; h < 2; h++) {
        int i = tid + h * 512;
        g_thr[f * U_ + i] = expf(key[i]);     // thr = exp(-w), ascending
        g_es [f * U_ + i] = expf(-key[i]);    // e = exp(w)
        g_ord[f * U_ + i] = idx[i];
    }

    // zero logits slice
    for (int i = tid; i < (B_ * C_) / F_; i += 512)
        g_logits[f * ((B_ * C_) / F_) + i] = 0.0f;
    if (f == 0 && tid < C_) {
        float s = b_out[tid];
        for (int ff = 0; ff < F_; ff++) s += b2[ff * C_ + tid];
        g_bsum[tid] = s;
    }
    __syncthreads();   // done with key before reuse as reduction buffer

    // cont0[c] = sum_v relu(b1[f,v]) * W2[f,v,c]
    float r = fmaxf(b1[f * V_ + (tid & 511)], 0.0f);
    for (int c = 0; c < C_; c++) {
        float contrib = (tid < 512) ? r * W2[((size_t)f * V_ + tid) * C_ + c] : 0.0f;
        key[tid] = contrib;
        __syncthreads();
        for (int s = 256; s > 0; s >>= 1) {
            if (tid < s) key[tid] += key[tid + s];
            __syncthreads();
        }
        if (tid == 0) g_cont0[f * C_ + c] = key[0];
        __syncthreads();
    }
}

// ---------------------------------------------------------------------------
// Kernel 1: build prefix tables. Grid (4, F_) = (v-chunk, f), 128 threads.
// Sequential scan over sorted units with cp.async double-buffered row staging.
// ---------------------------------------------------------------------------
__global__ void __launch_bounds__(128)
nam_build_kernel(const float* __restrict__ W1) {
    const int vc = blockIdx.x, f = blockIdx.y;
    const int tid = threadIdx.x;
    const int vb = vc * 128 + tid;

    __shared__ int   ord_s[1024];
    __shared__ float es_s[1024];
    __shared__ float ring[2][32 * 128];

    for (int i = tid; i < 1024; i += 128) {
        ord_s[i] = g_ord[f * U_ + i];
        es_s[i]  = g_es [f * U_ + i];
    }
    __syncthreads();

    const float* Wf = W1 + (size_t)f * U_ * V_;
    const uint32_t ring0 = smem_u32(&ring[0][0]);
    const uint32_t ring1 = smem_u32(&ring[1][0]);

    // issue segment seg into buffer b (32 rows x 4B per thread)
    auto issue = [&](int seg, int b) {
        uint32_t rb = b ? ring1 : ring0;
        #pragma unroll 8
        for (int r = 0; r < 32; r++) {
            int i = seg * 32 + r;
            cpa4(rb + (uint32_t)(r * 128 + tid) * 4u,
                 Wf + (size_t)ord_s[i] * V_ + vb);
        }
        CP_COMMIT();
    };

    float s1 = 0.0f, p2 = 0.0f;
    float2* tabf = g_tab + (size_t)f * 1025 * 512 + vb;

    issue(0, 0);
    for (int seg = 0; seg < 32; seg++) {
        if (seg < 31) { issue(seg + 1, (seg + 1) & 1); CP_WAIT(1); }
        else          { CP_WAIT(0); }
        const float* buf = ring[seg & 1];
        #pragma unroll 8
        for (int r = 0; r < 32; r++) {
            int i = seg * 32 + r;
            float w = buf[r * 128 + tid];
            tabf[(size_t)i * 512] = make_float2(s1, p2);
            s1 += w;
            p2 = fmaf(es_s[i], w, p2);
        }
    }
    tabf[(size_t)1024 * 512] = make_float2(s1, p2);
    g_T2[f * 512 + vb] = p2;
}

__global__ void nam_dummy_kernel() {}

// ---------------------------------------------------------------------------
// Kernel 3: main. Grid (B/256, F_), 256 threads; thread = one (b, f) query.
// val[v] = S1[j][v] + x~ * (T2[v] - P2[j][v]);  h2 = relu(val + b1);  p = h2@W2
// ---------------------------------------------------------------------------
__global__ void __launch_bounds__(256)
nam_main_kernel(const float* __restrict__ x,
                const float* __restrict__ exu_b,
                const float* __restrict__ b1,
                const float* __restrict__ W2) {
    const int f = blockIdx.y;
    const int tid = threadIdx.x;

    __shared__ float thr_s[1024];
    __shared__ float T2s[512];
    __shared__ float b1s[512];
    __shared__ float W2s[512 * 12];
    __shared__ float cont0s[12];

    for (int i = tid; i < 1024; i += 256) thr_s[i] = g_thr[f * U_ + i];
    for (int i = tid; i < 512; i += 256) {
        T2s[i] = g_T2[f * 512 + i];
        b1s[i] = b1[(size_t)f * V_ + i];
    }
    for (int i = tid; i < 512 * 12; i += 256) {
        int v = i / 12, c = i - v * 12;
        W2s[i] = (c < C_) ? W2[((size_t)f * V_ + v) * C_ + c] : 0.0f;
    }
    if (tid < C_) cont0s[tid] = g_cont0[f * C_ + tid];
    __syncthreads();

    const int b = blockIdx.x * 256 + tid;
    const float xt = x[(size_t)b * F_ + f] - exu_b[f];

    float p[10];
    if (xt <= 0.0f) {
        #pragma unroll
        for (int c = 0; c < 10; c++) p[c] = cont0s[c];
    } else {
        int lo = 0, hi = 1024;
        while (lo < hi) {
            int mid = (lo + hi) >> 1;
            if (thr_s[mid] <= xt) lo = mid + 1; else hi = mid;
        }
        #pragma unroll
        for (int c = 0; c < 10; c++) p[c] = 0.0f;

        const float4* row4 = (const float4*)(g_tab + ((size_t)f * 1025 + lo) * 512);
        const float2* T22  = (const float2*)T2s;
        const float2* b12  = (const float2*)b1s;

        #pragma unroll 4
        for (int v2 = 0; v2 < 256; v2++) {
            float4 q = row4[v2];                 // s1a, p2a, s1b, p2b
            float2 t2 = T22[v2], bb = b12[v2];
            float ha = fmaxf(fmaf(xt, t2.x - q.y, q.x) + bb.x, 0.0f);
            float hb = fmaxf(fmaf(xt, t2.y - q.w, q.z) + bb.y, 0.0f);
            const float4* wa = (const float4*)&W2s[(2 * v2) * 12];
            float4 a0 = wa[0], a1 = wa[1], a2 = wa[2];
            float4 c0 = wa[3], c1 = wa[4], c2 = wa[5];
            p[0] = fmaf(ha, a0.x, fmaf(hb, c0.x, p[0]));
            p[1] = fmaf(ha, a0.y, fmaf(hb, c0.y, p[1]));
            p[2] = fmaf(ha, a0.z, fmaf(hb, c0.z, p[2]));
            p[3] = fmaf(ha, a0.w, fmaf(hb, c0.w, p[3]));
            p[4] = fmaf(ha, a1.x, fmaf(hb, c1.x, p[4]));
            p[5] = fmaf(ha, a1.y, fmaf(hb, c1.y, p[5]));
            p[6] = fmaf(ha, a1.z, fmaf(hb, c1.z, p[6]));
            p[7] = fmaf(ha, a1.w, fmaf(hb, c1.w, p[7]));
            p[8] = fmaf(ha, a2.x, fmaf(hb, c2.x, p[8]));
            p[9] = fmaf(ha, a2.y, fmaf(hb, c2.y, p[9]));
        }
    }
    #pragma unroll
    for (int c = 0; c < 10; c++)
        atomicAdd(&g_logits[b * C_ + c], p[c]);
}

// ---------------------------------------------------------------------------
__global__ void nam_softmax_kernel(float* __restrict__ out) {
    int b = blockIdx.x * blockDim.x + threadIdx.x;
    if (b >= B_) return;
    float v[C_];
    float m = -1e30f;
    #pragma unroll
    for (int c = 0; c < C_; c++) {
        v[c] = g_logits[b * C_ + c] + g_bsum[c];
        m = fmaxf(m, v[c]);
    }
    float s = 0.0f;
    #pragma unroll
    for (int c = 0; c < C_; c++) { v[c] = expf(v[c] - m); s += v[c]; }
    float inv = 1.0f / s;
    #pragma unroll
    for (int c = 0; c < C_; c++) out[b * C_ + c] = v[c] * inv;
}

// ---------------------------------------------------------------------------
extern "C" void kernel_launch(void* const* d_in, const int* in_sizes, int n_in,
                              void* d_out, int out_size) {
    const float* x     = (const float*)d_in[0];
    const float* exu_w = (const float*)d_in[1];
    const float* exu_b = (const float*)d_in[2];
    const float* W1    = (const float*)d_in[3];
    const float* b1    = (const float*)d_in[4];
    const float* W2    = (const float*)d_in[5];
    const float* b2    = (const float*)d_in[6];
    const float* b_out = (const float*)d_in[7];
    float* out = (float*)d_out;

    nam_sort_kernel<<<F_, 512>>>(exu_w, b1, W2, b2, b_out);        // launch 0
    dim3 gbuild(4, F_);
    nam_build_kernel<<<gbuild, 128>>>(W1);                          // launch 1
    nam_dummy_kernel<<<1, 32>>>();                                  // launch 2 (ncu align)
    dim3 gmain(B_ / 256, F_);
    nam_main_kernel<<<gmain, 256>>>(x, exu_b, b1, W2);              // launch 3
    nam_softmax_kernel<<<(B_ + 255) / 256, 256>>>(out);             // launch 4
}

// round 13
// speedup vs baseline: 1.8362x; 1.8362x over previous
#include <cuda_runtime.h>
#include <math.h>
#include <stdint.h>

#define B_ 2048
#define F_ 128
#define U_ 1024
#define V_ 512
#define C_ 10

#define NG_ 128           // groups of 8 sorted units
#define WL_STRIDE 32768   // worklist region per phase-1 block (256 b x 128 f max)

// ---------------- global scratch ----------------
__device__ float  g_logits[B_ * C_];
__device__ float  g_bsum[C_];
__device__ float2 g_gsum[(size_t)F_ * NG_ * V_];   // per-group (S1,P2) sums  (67MB)
__device__ float2 g_tab8[(size_t)F_ * NG_ * V_];   // exclusive prefix at j=8*g (67MB)
__device__ float  g_S1tot[F_ * V_];
__device__ float  g_T2 [F_ * V_];
__device__ float  g_thr[F_ * U_];                  // sorted thresholds (asc)
__device__ float  g_es [F_ * U_];                  // e at sorted order
__device__ int    g_ord[F_ * U_];                  // original u index (sorted)
__device__ float  g_cont0[F_ * C_];                // x<=0 branch constant
__device__ float  g_cont1[F_ * C_];                // x>=thr_max branch constant
__device__ int    g_cntb[8];                       // per-phase1-block worklist counts
__device__ int    g_wbf[8 * WL_STRIDE];
__device__ float  g_wx [8 * WL_STRIDE];

// ---------------------------------------------------------------------------
// K0: per-feature sort (thr ascending) + cont0 + bsum + counter zero.
// ---------------------------------------------------------------------------
__global__ void __launch_bounds__(512)
nam_sort_kernel(const float* __restrict__ exu_w,
                const float* __restrict__ b1,
                const float* __restrict__ W2,
                const float* __restrict__ b2,
                const float* __restrict__ b_out) {
    const int f = blockIdx.x;
    const int tid = threadIdx.x;
    __shared__ float key[1024];
    __shared__ int   idx[1024];

    key[tid]       = -exu_w[f * U_ + tid];
    key[tid + 512] = -exu_w[f * U_ + tid + 512];
    idx[tid] = tid; idx[tid + 512] = tid + 512;
    __syncthreads();

    for (int k = 2; k <= 1024; k <<= 1) {
        for (int j = k >> 1; j > 0; j >>= 1) {
            #pragma unroll
            for (int h = 0; h < 2; h++) {
                int i = tid + h * 512;
                int ixj = i ^ j;
                if (ixj > i) {
                    bool up = ((i & k) == 0);
                    float a = key[i], b = key[ixj];
                    if ((a > b) == up) {
                        key[i] = b; key[ixj] = a;
                        int ti = idx[i]; idx[i] = idx[ixj]; idx[ixj] = ti;
                    }
                }
            }
            __syncthreads();
        }
    }

    #pragma unroll
    for (int h = 0; h < 2; h++) {
        int i = tid + h * 512;
        g_thr[f * U_ + i] = expf(key[i]);     // thr = exp(-w), ascending
        g_es [f * U_ + i] = expf(-key[i]);    // e = exp(w)
        g_ord[f * U_ + i] = idx[i];
    }

    if (f == 0 && tid < C_) {
        float s = b_out[tid];
        for (int ff = 0; ff < F_; ff++) s += b2[ff * C_ + tid];
        g_bsum[tid] = s;
    }
    if (f == 0 && tid >= 32 && tid < 40) g_cntb[tid - 32] = 0;
    __syncthreads();

    // cont0[c] = sum_v relu(b1) * W2
    float r = fmaxf(b1[f * V_ + tid], 0.0f);
    for (int c = 0; c < C_; c++) {
        key[tid] = r * W2[((size_t)f * V_ + tid) * C_ + c];
        __syncthreads();
        for (int s = 256; s > 0; s >>= 1) {
            if (tid < s) key[tid] += key[tid + s];
            __syncthreads();
        }
        if (tid == 0) g_cont0[f * C_ + c] = key[0];
        __syncthreads();
    }
}

// ---------------------------------------------------------------------------
// K1: per-group sums of 8 sorted W1 rows. Grid (4 vc, 128 g, 128 f), 128 thr.
// ---------------------------------------------------------------------------
__global__ void __launch_bounds__(128)
nam_segsum_kernel(const float* __restrict__ W1) {
    const int vc = blockIdx.x, g = blockIdx.y, f = blockIdx.z;
    const int v = vc * 128 + threadIdx.x;
    const float* Wf = W1 + (size_t)f * U_ * V_;

    float s1 = 0.0f, p2 = 0.0f;
    #pragma unroll
    for (int r = 0; r < 8; r++) {
        int i = g * 8 + r;
        int u = g_ord[f * U_ + i];
        float e = g_es[f * U_ + i];
        float w = Wf[(size_t)u * V_ + v];
        s1 += w;
        p2 = fmaf(e, w, p2);
    }
    g_gsum[((size_t)f * NG_ + g) * V_ + v] = make_float2(s1, p2);
}

// ---------------------------------------------------------------------------
// K2: exclusive prefix over groups -> tab8; totals -> S1tot, T2.
// Grid F_, 512 threads (thread = v).
// ---------------------------------------------------------------------------
__global__ void __launch_bounds__(512)
nam_prefix_kernel() {
    const int f = blockIdx.x;
    const int v = threadIdx.x;
    const float2* gs = g_gsum + (size_t)f * NG_ * V_ + v;
    float2*       tb = g_tab8 + (size_t)f * NG_ * V_ + v;

    float s1 = 0.0f, p2 = 0.0f;
    #pragma unroll 4
    for (int g = 0; g < NG_; g++) {
        float2 q = gs[(size_t)g * V_];
        tb[(size_t)g * V_] = make_float2(s1, p2);
        s1 += q.x;
        p2 += q.y;
    }
    g_S1tot[f * V_ + v] = s1;
    g_T2  [f * V_ + v] = p2;
}

// ---------------------------------------------------------------------------
// K3: cont1[c] = sum_v relu(S1tot + b1) * W2  (all-units-saturated branch)
// ---------------------------------------------------------------------------
__global__ void __launch_bounds__(512)
nam_cont1_kernel(const float* __restrict__ b1, const float* __restrict__ W2) {
    __shared__ float red[512];
    const int f = blockIdx.x, v = threadIdx.x;
    float r = fmaxf(g_S1tot[f * V_ + v] + b1[(size_t)f * V_ + v], 0.0f);
    for (int c = 0; c < C_; c++) {
        red[v] = r * W2[((size_t)f * V_ + v) * C_ + c];
        __syncthreads();
        for (int s = 256; s > 0; s >>= 1) {
            if (v < s) red[v] += red[v + s];
            __syncthreads();
        }
        if (v == 0) g_cont1[f * C_ + c] = red[0];
        __syncthreads();
    }
}

// ---------------------------------------------------------------------------
// K4 phase1: thread = batch row; accumulate fast branches over all 128 f,
// append partial queries to this block's worklist region. Grid 8 x 256.
// ---------------------------------------------------------------------------
__global__ void __launch_bounds__(256)
nam_phase1_kernel(const float* __restrict__ x, const float* __restrict__ exu_b) {
    __shared__ float c0s[F_ * C_];
    __shared__ float c1s[F_ * C_];
    __shared__ float tms[F_];
    __shared__ float ebs[F_];
    __shared__ int   scnt;

    const int tid = threadIdx.x;
    for (int i = tid; i < F_ * C_; i += 256) { c0s[i] = g_cont0[i]; c1s[i] = g_cont1[i]; }
    for (int i = tid; i < F_; i += 256) { tms[i] = g_thr[i * U_ + 1023]; ebs[i] = exu_b[i]; }
    if (tid == 0) scnt = 0;
    __syncthreads();

    const int b = blockIdx.x * 256 + tid;
    const int wbase = blockIdx.x * WL_STRIDE;
    float acc[10];
    #pragma unroll
    for (int c = 0; c < 10; c++) acc[c] = 0.0f;

    for (int f = 0; f < F_; f++) {
        float xt = x[(size_t)b * F_ + f] - ebs[f];
        if (xt <= 0.0f) {
            #pragma unroll
            for (int c = 0; c < 10; c++) acc[c] += c0s[f * C_ + c];
        } else if (xt >= tms[f]) {
            #pragma unroll
            for (int c = 0; c < 10; c++) acc[c] += c1s[f * C_ + c];
        } else {
            int w = atomicAdd(&scnt, 1);
            g_wbf[wbase + w] = (b << 7) | f;
            g_wx [wbase + w] = xt;
        }
    }
    #pragma unroll
    for (int c = 0; c < 10; c++) g_logits[b * C_ + c] = acc[c];

    __syncthreads();
    if (tid == 0) g_cntb[blockIdx.x] = scnt;
}

// ---------------------------------------------------------------------------
// K5 phase2: one warp per partial query. Warp 32-ary search for j, base row
// from tab8, <=7 exact W1-row corrections, fused relu+W2, atomic into logits.
// ---------------------------------------------------------------------------
__global__ void __launch_bounds__(256)
nam_phase2_kernel(const float* __restrict__ W1,
                  const float* __restrict__ b1,
                  const float* __restrict__ W2) {
    const int wid_g = (blockIdx.x * 256 + threadIdx.x) >> 5;
    const int lane = threadIdx.x & 31;
    const int nw = gridDim.x * 8;

    for (int rgn = 0; rgn < 8; rgn++) {
        const int cnt = g_cntb[rgn];
        for (int w = wid_g; w < cnt; w += nw) {
            const int bf = g_wbf[rgn * WL_STRIDE + w];
            const float xt = g_wx[rgn * WL_STRIDE + w];
            const int b = bf >> 7, f = bf & 127;

            // warp-cooperative 32-ary search: j = #{thr <= xt}
            const float* thrf = g_thr + f * U_;
            float v1 = thrf[lane * 32 + 31];
            unsigned m1 = __ballot_sync(0xffffffffu, v1 <= xt);
            int s = __popc(m1);                     // s < 32 guaranteed (xt < thr[1023])
            float v2 = thrf[s * 32 + lane];
            unsigned m2 = __ballot_sync(0xffffffffu, v2 <= xt);
            int j = s * 32 + __popc(m2);            // 0..1023
            int sb = j >> 3;

            float s1[16], p2[16];
            const float2* trow = g_tab8 + ((size_t)f * NG_ + sb) * V_;
            #pragma unroll
            for (int k = 0; k < 16; k++) {
                float2 q = trow[k * 32 + lane];
                s1[k] = q.x; p2[k] = q.y;
            }
            // corrections: sorted units [8*sb, j) are saturated beyond the base row
            for (int i = sb * 8; i < j; i++) {
                int u = g_ord[f * U_ + i];
                float e = g_es[f * U_ + i];
                const float* wr = W1 + ((size_t)f * U_ + u) * V_;
                #pragma unroll
                for (int k = 0; k < 16; k++) {
                    float wv = wr[k * 32 + lane];
                    s1[k] += wv;
                    p2[k] = fmaf(e, wv, p2[k]);
                }
            }

            float p[10];
            #pragma unroll
            for (int c = 0; c < 10; c++) p[c] = 0.0f;
            #pragma unroll
            for (int k = 0; k < 16; k++) {
                int v = k * 32 + lane;
                float t2 = g_T2[f * V_ + v];
                float val = fmaf(xt, t2 - p2[k], s1[k]);
                float h2 = fmaxf(val + b1[(size_t)f * V_ + v], 0.0f);
                const float* w2 = W2 + ((size_t)f * V_ + v) * C_;
                #pragma unroll
                for (int c = 0; c < 10; c++) p[c] = fmaf(h2, w2[c], p[c]);
            }
            #pragma unroll
            for (int o = 16; o > 0; o >>= 1)
                #pragma unroll
                for (int c = 0; c < 10; c++)
                    p[c] += __shfl_xor_sync(0xffffffffu, p[c], o);
            #pragma unroll
            for (int c = 0; c < 10; c++)
                if (lane == c) atomicAdd(&g_logits[b * C_ + c], p[c]);
        }
    }
}

// ---------------------------------------------------------------------------
__global__ void nam_softmax_kernel(float* __restrict__ out) {
    int b = blockIdx.x * blockDim.x + threadIdx.x;
    if (b >= B_) return;
    float v[C_];
    float m = -1e30f;
    #pragma unroll
    for (int c = 0; c < C_; c++) {
        v[c] = g_logits[b * C_ + c] + g_bsum[c];
        m = fmaxf(m, v[c]);
    }
    float s = 0.0f;
    #pragma unroll
    for (int c = 0; c < C_; c++) { v[c] = expf(v[c] - m); s += v[c]; }
    float inv = 1.0f / s;
    #pragma unroll
    for (int c = 0; c < C_; c++) out[b * C_ + c] = v[c] * inv;
}

// ---------------------------------------------------------------------------
extern "C" void kernel_launch(void* const* d_in, const int* in_sizes, int n_in,
                              void* d_out, int out_size) {
    const float* x     = (const float*)d_in[0];
    const float* exu_w = (const float*)d_in[1];
    const float* exu_b = (const float*)d_in[2];
    const float* W1    = (const float*)d_in[3];
    const float* b1    = (const float*)d_in[4];
    const float* W2    = (const float*)d_in[5];
    const float* b2    = (const float*)d_in[6];
    const float* b_out = (const float*)d_in[7];
    float* out = (float*)d_out;

    nam_sort_kernel<<<F_, 512>>>(exu_w, b1, W2, b2, b_out);   // 0
    dim3 gseg(4, NG_, F_);
    nam_segsum_kernel<<<gseg, 128>>>(W1);                     // 1
    nam_prefix_kernel<<<F_, 512>>>();                         // 2
    nam_cont1_kernel<<<F_, 512>>>(b1, W2);                    // 3
    nam_phase1_kernel<<<8, 256>>>(x, exu_b);                  // 4
    nam_phase2_kernel<<<256, 256>>>(W1, b1, W2);              // 5
    nam_softmax_kernel<<<(B_ + 255) / 256, 256>>>(out);       // 6
}